// round 2
// baseline (speedup 1.0000x reference)
#include <cuda_runtime.h>
#include <cuda_bf16.h>

#define N_NODES   8192
#define FLOW_ITERS 10
#define NUM_FUSED  9          // 9 scatter+update rounds
#define GRID      512
#define BLOCK     256

// Scratch state (module-lifetime; left in a clean state by every kernel so the
// graph replays deterministically).
__device__ float        g_adj[N_NODES];
__device__ float        g_inflow[N_NODES];     // zero at every kernel entry
__device__ unsigned int g_done;                // zero at every kernel entry

// One fused round:
//   phase A: scatter  inflow[c[e]] += v[e] * adj_src(r[e])     (grid-stride)
//   phase B: zero this round's 1/9 slice of the 256MB output   (grid-stride, streaming)
//   tail  : LAST block to finish does adj = relu(inflow - d), inflow = 0,
//           and resets the done-counter.
// Iteration 0 computes the adjacency inline: adj_1(r) = relu(-demands[r]).
__global__ void __launch_bounds__(BLOCK)
k_fused(const int*   __restrict__ rows,
        const int*   __restrict__ cols,
        const float* __restrict__ values,
        const float* __restrict__ demands,
        float4*      __restrict__ out4,
        int e4, size_t z_lo, size_t z_hi, int first_iter)
{
    const int tid     = blockIdx.x * blockDim.x + threadIdx.x;
    const int nthread = gridDim.x * blockDim.x;

    // ---- phase A: edge scatter ----
    for (int t = tid; t < e4; t += nthread) {
        int4   r = __ldg(((const int4*)rows)   + t);
        int4   c = __ldg(((const int4*)cols)   + t);
        float4 v = __ldg(((const float4*)values) + t);
        float ax, ay, az, aw;
        if (first_iter) {
            ax = fmaxf(-__ldg(&demands[r.x]), 0.0f);
            ay = fmaxf(-__ldg(&demands[r.y]), 0.0f);
            az = fmaxf(-__ldg(&demands[r.z]), 0.0f);
            aw = fmaxf(-__ldg(&demands[r.w]), 0.0f);
        } else {
            ax = __ldg(&g_adj[r.x]);
            ay = __ldg(&g_adj[r.y]);
            az = __ldg(&g_adj[r.z]);
            aw = __ldg(&g_adj[r.w]);
        }
        atomicAdd(&g_inflow[c.x], v.x * ax);
        atomicAdd(&g_inflow[c.y], v.y * ay);
        atomicAdd(&g_inflow[c.z], v.z * az);
        atomicAdd(&g_inflow[c.w], v.w * aw);
    }

    // ---- phase B: zero a slice of the output (streaming stores) ----
    const float4 z = make_float4(0.f, 0.f, 0.f, 0.f);
    for (size_t i = z_lo + tid; i < z_hi; i += (size_t)nthread)
        __stcs(out4 + i, z);

    // ---- tail: last finishing block performs the node update ----
    __shared__ int s_last;
    __threadfence();                    // make our inflow atomics + stores visible
    __syncthreads();
    if (threadIdx.x == 0) {
        unsigned int prev = atomicAdd(&g_done, 1u);
        s_last = (prev == (unsigned int)(gridDim.x - 1)) ? 1 : 0;
    }
    __syncthreads();
    if (s_last) {
        // all other blocks' scatter work is complete and fenced
        for (int i = threadIdx.x; i < N_NODES; i += blockDim.x) {
            g_adj[i]    = fmaxf(g_inflow[i] - __ldg(&demands[i]), 0.0f);
            g_inflow[i] = 0.0f;
        }
        __syncthreads();
        if (threadIdx.x == 0) g_done = 0;   // reset for next kernel / next replay
    }
}

// out[rows[e], cols[e]] += values[e] * adj_final[rows[e]]
__global__ void __launch_bounds__(BLOCK)
k_final(const int*   __restrict__ rows,
        const int*   __restrict__ cols,
        const float* __restrict__ values,
        float*       __restrict__ out,
        int e4)
{
    int t = blockIdx.x * blockDim.x + threadIdx.x;
    if (t < e4) {
        int4   r = __ldg(((const int4*)rows)   + t);
        int4   c = __ldg(((const int4*)cols)   + t);
        float4 v = __ldg(((const float4*)values) + t);
        atomicAdd(out + (size_t)r.x * N_NODES + c.x, v.x * __ldg(&g_adj[r.x]));
        atomicAdd(out + (size_t)r.y * N_NODES + c.y, v.y * __ldg(&g_adj[r.y]));
        atomicAdd(out + (size_t)r.z * N_NODES + c.z, v.z * __ldg(&g_adj[r.z]));
        atomicAdd(out + (size_t)r.w * N_NODES + c.w, v.w * __ldg(&g_adj[r.w]));
    }
}

extern "C" void kernel_launch(void* const* d_in, const int* in_sizes, int n_in,
                              void* d_out, int out_size) {
    const float* values  = (const float*)d_in[0];
    const float* demands = (const float*)d_in[1];
    const int*   rows    = (const int*)d_in[2];
    const int*   cols    = (const int*)d_in[3];
    float*       out     = (float*)d_out;

    const int    E  = in_sizes[0];            // 262144
    const int    e4 = E / 4;                  // 65536
    const size_t n4 = (size_t)out_size / 4;   // 16777216 float4s (256 MB)

    // 9 fused rounds; round i also zeroes slice [i/9, (i+1)/9) of the output.
    for (int it = 0; it < NUM_FUSED; ++it) {
        size_t z_lo = n4 * (size_t)it       / NUM_FUSED;
        size_t z_hi = n4 * (size_t)(it + 1) / NUM_FUSED;
        k_fused<<<GRID, BLOCK>>>(rows, cols, values, demands, (float4*)out,
                                 e4, z_lo, z_hi, it == 0 ? 1 : 0);
    }

    // flow_10 scattered into the (fully zeroed) dense output
    k_final<<<(e4 + BLOCK - 1) / BLOCK, BLOCK>>>(rows, cols, values, out, e4);
}

// round 3
// speedup vs baseline: 1.4067x; 1.4067x over previous
#include <cuda_runtime.h>
#include <cuda_bf16.h>

#define N_NODES    8192
#define FLOW_ITERS 10
#define ROUNDS     9            // scatter+update rounds (adj_1 -> adj_10)
#define FB         32           // flow-worker blocks
#define GRID       148          // exactly one wave on 148+ SMs
#define BLOCK      1024
#define NODES_PER_FLOW_BLOCK (N_NODES / FB)   // 256

// Monotonic barrier counters (2 per round). Zero-initialized at module load;
// k_final resets them after every pass so graph replays are deterministic.
__device__ unsigned int g_bar[2 * ROUNDS];
__device__ float g_adj[N_NODES];
__device__ float g_inflow[N_NODES];   // reset slice-wise inside each update phase

// Arrive-and-spin barrier among the FB flow blocks. Counters are monotonic
// within one kernel execution (never reset here -> no reset/spin race).
__device__ __forceinline__ void flow_barrier(int b) {
    __syncthreads();
    if (threadIdx.x == 0) {
        __threadfence();                       // publish our scatter/update writes
        atomicAdd(&g_bar[b], 1u);
        volatile unsigned int* p = &g_bar[b];
        while (*p < FB) __nanosleep(64);
        __threadfence();                       // acquire side
    }
    __syncthreads();
}

__global__ void __launch_bounds__(BLOCK, 1)
k_mega(const int*   __restrict__ rows,
       const int*   __restrict__ cols,
       const float* __restrict__ values,
       const float* __restrict__ demands,
       float4*      __restrict__ out4,
       int e4, size_t n4)
{
    if (blockIdx.x >= FB) {
        // ───────── zero workers: stream 256MB of zeros, no fences ─────────
        const size_t zt     = (size_t)(blockIdx.x - FB) * BLOCK + threadIdx.x;
        const size_t stride = (size_t)(GRID - FB) * BLOCK;
        const float4 z = make_float4(0.f, 0.f, 0.f, 0.f);
        for (size_t i = zt; i < n4; i += stride)
            out4[i] = z;
        return;
    }

    // ───────────────────────── flow workers ─────────────────────────
    __shared__ float s_d[N_NODES];             // demands, block-private copy
    for (int i = threadIdx.x; i < N_NODES; i += BLOCK)
        s_d[i] = demands[i];
    __syncthreads();

    const int ftid    = blockIdx.x * BLOCK + threadIdx.x;   // 0 .. FB*BLOCK-1
    const int fstride = FB * BLOCK;

    volatile float* v_adj = g_adj;
    volatile float* v_inf = g_inflow;

    for (int it = 0; it < ROUNDS; ++it) {
        // scatter: inflow[c] += v * adj(r)
        for (int t = ftid; t < e4; t += fstride) {
            int4   r = __ldg(((const int4*)rows)   + t);
            int4   c = __ldg(((const int4*)cols)   + t);
            float4 v = __ldg(((const float4*)values) + t);
            float ax, ay, az, aw;
            if (it == 0) {                     // adj_1 = relu(-d)
                ax = fmaxf(-s_d[r.x], 0.0f);
                ay = fmaxf(-s_d[r.y], 0.0f);
                az = fmaxf(-s_d[r.z], 0.0f);
                aw = fmaxf(-s_d[r.w], 0.0f);
            } else {                           // volatile -> always fresh from L2
                ax = v_adj[r.x];
                ay = v_adj[r.y];
                az = v_adj[r.z];
                aw = v_adj[r.w];
            }
            atomicAdd(&g_inflow[c.x], v.x * ax);
            atomicAdd(&g_inflow[c.y], v.y * ay);
            atomicAdd(&g_inflow[c.z], v.z * az);
            atomicAdd(&g_inflow[c.w], v.w * aw);
        }

        flow_barrier(2 * it);                  // all scatters of round `it` done

        // update own node slice: adj = relu(inflow - d); inflow = 0
        if (threadIdx.x < NODES_PER_FLOW_BLOCK) {
            int i = blockIdx.x * NODES_PER_FLOW_BLOCK + threadIdx.x;
            float inf = v_inf[i];              // sole owner of this slice now
            g_adj[i]    = fmaxf(inf - s_d[i], 0.0f);
            g_inflow[i] = 0.0f;
        }

        flow_barrier(2 * it + 1);              // adj ready, inflow reset
    }
}

// out[r, c] += v * adj_10[r]; also reset barrier counters for the next replay.
__global__ void __launch_bounds__(256)
k_final(const int*   __restrict__ rows,
        const int*   __restrict__ cols,
        const float* __restrict__ values,
        float*       __restrict__ out,
        int e4)
{
    int t = blockIdx.x * blockDim.x + threadIdx.x;
    if (blockIdx.x == 0 && threadIdx.x < 2 * ROUNDS)
        g_bar[threadIdx.x] = 0u;
    if (t < e4) {
        int4   r = __ldg(((const int4*)rows)   + t);
        int4   c = __ldg(((const int4*)cols)   + t);
        float4 v = __ldg(((const float4*)values) + t);
        atomicAdd(out + (size_t)r.x * N_NODES + c.x, v.x * __ldg(&g_adj[r.x]));
        atomicAdd(out + (size_t)r.y * N_NODES + c.y, v.y * __ldg(&g_adj[r.y]));
        atomicAdd(out + (size_t)r.z * N_NODES + c.z, v.z * __ldg(&g_adj[r.z]));
        atomicAdd(out + (size_t)r.w * N_NODES + c.w, v.w * __ldg(&g_adj[r.w]));
    }
}

extern "C" void kernel_launch(void* const* d_in, const int* in_sizes, int n_in,
                              void* d_out, int out_size) {
    const float* values  = (const float*)d_in[0];
    const float* demands = (const float*)d_in[1];
    const int*   rows    = (const int*)d_in[2];
    const int*   cols    = (const int*)d_in[3];
    float*       out     = (float*)d_out;

    const int    E  = in_sizes[0];            // 262144
    const int    e4 = E / 4;                  // 65536
    const size_t n4 = (size_t)out_size / 4;   // 16777216 float4s (256 MB)

    k_mega<<<GRID, BLOCK>>>(rows, cols, values, demands, (float4*)out, e4, n4);
    k_final<<<(e4 + 255) / 256, 256>>>(rows, cols, values, out, e4);
}